// round 8
// baseline (speedup 1.0000x reference)
#include <cuda_runtime.h>
#include <cuda_bf16.h>
#include <cstdint>

// Problem constants
#define BB      4
#define TT_ALL  512
#define SS      512
#define IN_DIM  512
#define MEM_DIM 256

// Scratch (device globals; no allocations allowed)
__device__ __align__(16) float g_wq[BB * TT_ALL * MEM_DIM];   // [B,T,256]
__device__ __align__(16) float g_uh[BB * SS * MEM_DIM];       // [B,S,256]
__device__ __align__(16) float g_c [BB * TT_ALL * MEM_DIM];   // [B,T,256]

// ---------------------------------------------------------------------------
// TF32 tensor-core NT GEMM:  C[M,N] = Acat[M,K] * B[N,K]^T (+bias)
// CTA tile 64x64, BK=32, 256 threads = 8 warps (4m x 2n), warp tile 16x32.
// Static smem 36 KB. Dual-A supported (K1 % 32 == 0).
// ---------------------------------------------------------------------------
#define GBM 64
#define GBN 64
#define GBK 32
#define SPITCH 36

__device__ __forceinline__ uint32_t f2tf32(float f) {
    uint32_t o;
    asm("cvt.rna.tf32.f32 %0, %1;" : "=r"(o) : "f"(f));
    return o;
}

__device__ __forceinline__ void mma_tf32(
    float& c0, float& c1, float& c2, float& c3,
    uint32_t a0, uint32_t a1, uint32_t a2, uint32_t a3,
    uint32_t b0, uint32_t b1)
{
    asm volatile(
        "mma.sync.aligned.m16n8k8.row.col.f32.tf32.tf32.f32 "
        "{%0,%1,%2,%3}, {%4,%5,%6,%7}, {%8,%9}, {%0,%1,%2,%3};\n"
        : "+f"(c0), "+f"(c1), "+f"(c2), "+f"(c3)
        : "r"(a0), "r"(a1), "r"(a2), "r"(a3), "r"(b0), "r"(b1));
}

struct GemmSmem {
    float As[2][GBM][SPITCH];   // 18 KB
    float Bs[2][GBN][SPITCH];   // 18 KB
};

__device__ __forceinline__ void store_tf32_4(float* p, float4 v) {
    p[0] = __uint_as_float(f2tf32(v.x));
    p[1] = __uint_as_float(f2tf32(v.y));
    p[2] = __uint_as_float(f2tf32(v.z));
    p[3] = __uint_as_float(f2tf32(v.w));
}

__device__ __forceinline__ void gemm_body(
    GemmSmem* sm,
    const float* __restrict__ A, const float* __restrict__ A2, int K1,
    const float* __restrict__ Bm, const float* __restrict__ bias,
    float* __restrict__ C, int N, int K, int row0, int col0)
{
    const int tid  = threadIdx.x;
    const int wid  = tid >> 5;
    const int lane = tid & 31;
    const int g    = lane >> 2;         // 0..7
    const int t    = lane & 3;          // 0..3
    const int wrow = (wid & 3) * 16;    // 0,16,32,48
    const int wcol = (wid >> 2) * 32;   // 0,32

    // staging: 512 float4 per matrix over 256 threads -> 2 each
    const int srow = tid >> 3;          // 0..31 (j-loop adds +32)
    const int sc4  = (tid & 7) * 4;     // 0..28 step 4

    const int K2 = K - K1;
    const int NP = K / GBK;

    float acc[4][4];
#pragma unroll
    for (int nt = 0; nt < 4; nt++)
#pragma unroll
        for (int i = 0; i < 4; i++) acc[nt][i] = 0.f;

    float4 ra[2], rb[2];

    // --- load panel 0 into regs, store to buf 0 (K1 >= GBK always) ---
    {
#pragma unroll
        for (int j = 0; j < 2; j++) {
            ra[j] = *reinterpret_cast<const float4*>(
                A + (size_t)(row0 + srow + 32 * j) * K1 + sc4);
            rb[j] = *reinterpret_cast<const float4*>(
                Bm + (size_t)(col0 + srow + 32 * j) * K + sc4);
        }
#pragma unroll
        for (int j = 0; j < 2; j++) {
            store_tf32_4(&sm->As[0][srow + 32 * j][sc4], ra[j]);
            store_tf32_4(&sm->Bs[0][srow + 32 * j][sc4], rb[j]);
        }
    }
    __syncthreads();

    for (int p = 0; p < NP; p++) {
        // prefetch next panel into regs
        if (p + 1 < NP) {
            const int k0 = (p + 1) * GBK;
            const float* srcA = A; int pitchA = K1; int kcolA = k0;
            if (A2 != nullptr && k0 >= K1) { srcA = A2; pitchA = K2; kcolA = k0 - K1; }
#pragma unroll
            for (int j = 0; j < 2; j++) {
                ra[j] = *reinterpret_cast<const float4*>(
                    srcA + (size_t)(row0 + srow + 32 * j) * pitchA + kcolA + sc4);
                rb[j] = *reinterpret_cast<const float4*>(
                    Bm + (size_t)(col0 + srow + 32 * j) * K + k0 + sc4);
            }
        }

        // compute on buffer p&1
        const float* ab = &sm->As[p & 1][0][0];
        const float* bb = &sm->Bs[p & 1][0][0];
#pragma unroll
        for (int kk = 0; kk < GBK; kk += 8) {
            uint32_t af[4], bf[4][2];
            {
                const int r = wrow + g;
                af[0] = __float_as_uint(ab[(r)     * SPITCH + kk + t]);
                af[1] = __float_as_uint(ab[(r + 8) * SPITCH + kk + t]);
                af[2] = __float_as_uint(ab[(r)     * SPITCH + kk + t + 4]);
                af[3] = __float_as_uint(ab[(r + 8) * SPITCH + kk + t + 4]);
            }
#pragma unroll
            for (int nt = 0; nt < 4; nt++) {
                const int n = wcol + 8 * nt + g;
                bf[nt][0] = __float_as_uint(bb[n * SPITCH + kk + t]);
                bf[nt][1] = __float_as_uint(bb[n * SPITCH + kk + t + 4]);
            }
#pragma unroll
            for (int nt = 0; nt < 4; nt++)
                mma_tf32(acc[nt][0], acc[nt][1], acc[nt][2], acc[nt][3],
                         af[0], af[1], af[2], af[3],
                         bf[nt][0], bf[nt][1]);
        }

        // store prefetched panel to the other buffer
        if (p + 1 < NP) {
            const int nb = (p + 1) & 1;
#pragma unroll
            for (int j = 0; j < 2; j++) {
                store_tf32_4(&sm->As[nb][srow + 32 * j][sc4], ra[j]);
                store_tf32_4(&sm->Bs[nb][srow + 32 * j][sc4], rb[j]);
            }
        }
        __syncthreads();
    }

    // epilogue
    {
        const int row_a = row0 + wrow + g;
        const int row_b = row_a + 8;
#pragma unroll
        for (int nt = 0; nt < 4; nt++) {
            const int col = col0 + wcol + 8 * nt + 2 * t;
            float b0v = 0.f, b1v = 0.f;
            if (bias != nullptr) { b0v = bias[col]; b1v = bias[col + 1]; }
            C[(size_t)row_a * N + col]     = acc[nt][0] + b0v;
            C[(size_t)row_a * N + col + 1] = acc[nt][1] + b1v;
            C[(size_t)row_b * N + col]     = acc[nt][2] + b0v;
            C[(size_t)row_b * N + col + 1] = acc[nt][3] + b1v;
        }
    }
}

// merged k1+k2: grid (4, 64). by<32 -> wq GEMM, else uh GEMM.
__global__ __launch_bounds__(256) void gemm_k1k2_kernel(
    const float* __restrict__ inputs, const float* __restrict__ Wq,
    const float* __restrict__ mems,   const float* __restrict__ Wc,
    const float* __restrict__ bc,
    float* __restrict__ owq, float* __restrict__ ouh)
{
    __shared__ GemmSmem sm;
    const int bx = blockIdx.x, by = blockIdx.y;
    if (by < 32) {
        gemm_body(&sm, inputs, nullptr, IN_DIM, Wq, nullptr, owq,
                  MEM_DIM, IN_DIM, by * GBM, bx * GBN);
    } else {
        gemm_body(&sm, mems, nullptr, MEM_DIM, Wc, bc, ouh,
                  MEM_DIM, MEM_DIM, (by - 32) * GBM, bx * GBN);
    }
}

// k4: dual-A output projection. grid (8, 32)
__global__ __launch_bounds__(256) void gemm_out_kernel(
    const float* __restrict__ Cmat, const float* __restrict__ inputs,
    const float* __restrict__ Wout, const float* __restrict__ bout,
    float* __restrict__ attn_h)
{
    __shared__ GemmSmem sm;
    gemm_body(&sm, Cmat, inputs, MEM_DIM, Wout, bout, attn_h,
              IN_DIM, MEM_DIM + IN_DIM, blockIdx.y * GBM, blockIdx.x * GBN);
}

// ---------------------------------------------------------------------------
// Fused attention core (unchanged from R7): scores -> tanh -> dot(v) ->
// masked softmax -> tensor-core context. Grid (37, B) = 148 CTAs, 512 thr.
// ---------------------------------------------------------------------------
#define TTILE 14
#define NTILES_T 37
#define DTILE 16
#define UPITCH 20
#define UBUF_ELEMS (SS * UPITCH)
#define PBP   520
#define MROWS 32
#define MPITCH 264
#define MBUF_ELEMS (MROWS * MPITCH)
#define ATTN_SMEM_FLOATS (2 * UBUF_ELEMS + TTILE * MEM_DIM + MEM_DIM + TTILE * 16 \
                          + 2 * MBUF_ELEMS)
#define ATTN_SMEM_BYTES  (ATTN_SMEM_FLOATS * 4)

__device__ __forceinline__ float tanh_fast(float x) {
    float y;
    asm("tanh.approx.f32 %0, %1;" : "=f"(y) : "f"(x));
    return y;
}

__device__ __forceinline__ void cp_async16(void* sdst, const void* gsrc) {
    uint32_t sa = (uint32_t)__cvta_generic_to_shared(sdst);
    asm volatile("cp.async.ca.shared.global [%0], [%1], 16;\n" :: "r"(sa), "l"(gsrc));
}
#define CP_COMMIT()  asm volatile("cp.async.commit_group;\n")
#define CP_WAIT(N)   asm volatile("cp.async.wait_group %0;\n" :: "n"(N))

__device__ __forceinline__ void prefetch_uh(
    const float* __restrict__ uh_b, float* ubuf, int d0, int tid)
{
    const int c  = tid & 3;
    const int s0 = tid >> 2;
#pragma unroll
    for (int it = 0; it < 4; it++) {
        const int s = s0 + it * 128;
        cp_async16(ubuf + s * UPITCH + c * 4,
                   uh_b + ((size_t)s << 8) + d0 + c * 4);
    }
}

__device__ __forceinline__ void stage_mems(
    const float* __restrict__ memb, float* mbuf, int chunk, int tid)
{
#pragma unroll
    for (int j = 0; j < 4; j++) {
        const int i  = tid + j * 512;
        const int r  = i >> 6;
        const int c4 = (i & 63) * 4;
        cp_async16(mbuf + r * MPITCH + c4,
                   memb + ((size_t)(chunk * MROWS + r) << 8) + c4);
    }
}

__global__ __launch_bounds__(512) void attn_core_kernel(
    const float* __restrict__ wq,        // [B,T,256]
    const float* __restrict__ uh,        // [B,S,256]
    const float* __restrict__ mems,      // [B,S,256]
    const int*   __restrict__ mem_masks, // [B]
    const float* __restrict__ v,         // [256]
    float* __restrict__ align_out,       // [B,T,S]
    float* __restrict__ c_out)           // [B,T,256]
{
    extern __shared__ float sdyn[];
    float* ubuf0 = sdyn;
    float* ubuf1 = sdyn + UBUF_ELEMS;
    float* wq_s  = sdyn + 2 * UBUF_ELEMS;
    float* v_s   = wq_s + TTILE * MEM_DIM;
    float* red_s = v_s + MEM_DIM;
    float* mbuf0 = red_s + TTILE * 16;
    float* mbuf1 = mbuf0 + MBUF_ELEMS;
    float* pbuf  = ubuf0;

    const int tid  = threadIdx.x;
    const int b    = blockIdx.y;
    const int t0   = blockIdx.x * TTILE;
    const int my_s = tid;
    const int lane = tid & 31;
    const int wid  = tid >> 5;

    const float* uh_b = uh + ((size_t)b * SS << 8);

    prefetch_uh(uh_b, ubuf0, 0, tid);
    CP_COMMIT();

    for (int i = tid; i < TTILE * 64; i += 512) {
        const int t  = i >> 6;
        const int c4 = (i & 63) * 4;
        float4 val = make_float4(0.f, 0.f, 0.f, 0.f);
        if (t0 + t < TT_ALL)
            val = *reinterpret_cast<const float4*>(
                wq + ((size_t)(b * TT_ALL + t0 + t) << 8) + c4);
        *reinterpret_cast<float4*>(wq_s + t * MEM_DIM + c4) = val;
    }
    if (tid < 64)
        *reinterpret_cast<float4*>(v_s + tid * 4) =
            *reinterpret_cast<const float4*>(v + tid * 4);

    const int mlen = mem_masks[b];

    float acc[TTILE];
#pragma unroll
    for (int t = 0; t < TTILE; t++) acc[t] = 0.f;

#pragma unroll 1
    for (int tile = 0; tile < MEM_DIM / DTILE; tile++) {
        const int d0 = tile * DTILE;
        if (tile + 1 < MEM_DIM / DTILE) {
            prefetch_uh(uh_b, (tile & 1) ? ubuf0 : ubuf1, d0 + DTILE, tid);
            CP_COMMIT();
            CP_WAIT(1);
        } else {
            CP_WAIT(0);
        }
        __syncthreads();

        const float* ub = ((tile & 1) ? ubuf1 : ubuf0) + my_s * UPITCH;
#pragma unroll
        for (int q = 0; q < 4; q++) {
            const float4 u4 = *reinterpret_cast<const float4*>(ub + q * 4);
            const float4 v4 = *reinterpret_cast<const float4*>(v_s + d0 + q * 4);
#pragma unroll
            for (int t = 0; t < TTILE; t++) {
                const float4 w4 = *reinterpret_cast<const float4*>(
                    wq_s + t * MEM_DIM + d0 + q * 4);
                float a = acc[t];
                a = fmaf(tanh_fast(w4.x + u4.x), v4.x, a);
                a = fmaf(tanh_fast(w4.y + u4.y), v4.y, a);
                a = fmaf(tanh_fast(w4.z + u4.z), v4.z, a);
                a = fmaf(tanh_fast(w4.w + u4.w), v4.w, a);
                acc[t] = a;
            }
        }
        __syncthreads();
    }

    const bool valid = (my_s < mlen);
    float sc[TTILE];
#pragma unroll
    for (int t = 0; t < TTILE; t++) sc[t] = valid ? acc[t] : -1e30f;

    float mx[TTILE];
#pragma unroll
    for (int t = 0; t < TTILE; t++) {
        float m = sc[t];
#pragma unroll
        for (int o = 16; o > 0; o >>= 1) m = fmaxf(m, __shfl_xor_sync(0xffffffffu, m, o));
        if (lane == 0) red_s[t * 16 + wid] = m;
    }
    __syncthreads();
#pragma unroll
    for (int t = 0; t < TTILE; t++) {
        float m = red_s[t * 16];
#pragma unroll
        for (int i = 1; i < 16; i++) m = fmaxf(m, red_s[t * 16 + i]);
        mx[t] = m;
    }
    __syncthreads();

    float e[TTILE];
#pragma unroll
    for (int t = 0; t < TTILE; t++)
        e[t] = valid ? __expf(sc[t] - mx[t]) : 0.f;

#pragma unroll
    for (int t = 0; t < TTILE; t++) {
        float s = e[t];
#pragma unroll
        for (int o = 16; o > 0; o >>= 1) s += __shfl_xor_sync(0xffffffffu, s, o);
        if (lane == 0) red_s[t * 16 + wid] = s;
    }
    __syncthreads();

    float p[TTILE];
#pragma unroll
    for (int t = 0; t < TTILE; t++) {
        float s = 0.f;
#pragma unroll
        for (int i = 0; i < 16; i++) s += red_s[t * 16 + i];
        p[t] = e[t] * (1.0f / s);
    }

#pragma unroll
    for (int t = 0; t < TTILE; t++) {
        if (t0 + t < TT_ALL)
            align_out[((size_t)(b * TT_ALL + t0 + t) << 9) + my_s] = p[t];
        pbuf[t * PBP + my_s] = __uint_as_float(f2tf32(p[t]));
    }
    for (int i = tid; i < 2 * PBP; i += 512)
        pbuf[TTILE * PBP + i] = 0.f;
    __syncthreads();

    // ---- context via tensor cores ----
    const float* memb = mems + ((size_t)b * SS << 8);
    const int g  = lane >> 2;
    const int tq = lane & 3;
    const int wn = wid * 16;

    float ca[4] = {0.f, 0.f, 0.f, 0.f};
    float cb[4] = {0.f, 0.f, 0.f, 0.f};

    stage_mems(memb, mbuf0, 0, tid);
    CP_COMMIT();

#pragma unroll 1
    for (int ch = 0; ch < SS / MROWS; ch++) {
        if (ch + 1 < SS / MROWS) {
            stage_mems(memb, (ch & 1) ? mbuf0 : mbuf1, ch + 1, tid);
            CP_COMMIT();
            CP_WAIT(1);
        } else {
            CP_WAIT(0);
        }
        __syncthreads();

        const float* mb = (ch & 1) ? mbuf1 : mbuf0;
        const int sbase = ch * MROWS;
#pragma unroll
        for (int kk = 0; kk < MROWS; kk += 8) {
            const int sg = sbase + kk;
            uint32_t a0 = __float_as_uint(pbuf[(g)     * PBP + sg + tq]);
            uint32_t a1 = __float_as_uint(pbuf[(g + 8) * PBP + sg + tq]);
            uint32_t a2 = __float_as_uint(pbuf[(g)     * PBP + sg + tq + 4]);
            uint32_t a3 = __float_as_uint(pbuf[(g + 8) * PBP + sg + tq + 4]);

            uint32_t b0 = __float_as_uint(mb[(kk + tq)     * MPITCH + wn + g]);
            uint32_t b1 = __float_as_uint(mb[(kk + tq + 4) * MPITCH + wn + g]);
            mma_tf32(ca[0], ca[1], ca[2], ca[3], a0, a1, a2, a3, b0, b1);

            b0 = __float_as_uint(mb[(kk + tq)     * MPITCH + wn + 8 + g]);
            b1 = __float_as_uint(mb[(kk + tq + 4) * MPITCH + wn + 8 + g]);
            mma_tf32(cb[0], cb[1], cb[2], cb[3], a0, a1, a2, a3, b0, b1);
        }
        __syncthreads();
    }

    {
        const int row0g = t0 + g;
        if (row0g < TT_ALL) {
            float* dst = c_out + ((size_t)(b * TT_ALL + row0g) << 8);
            *reinterpret_cast<float2*>(dst + wn + 2 * tq)     = make_float2(ca[0], ca[1]);
            *reinterpret_cast<float2*>(dst + wn + 8 + 2 * tq) = make_float2(cb[0], cb[1]);
        }
        const int row1g = t0 + g + 8;
        if (g + 8 < TTILE && row1g < TT_ALL) {
            float* dst = c_out + ((size_t)(b * TT_ALL + row1g) << 8);
            *reinterpret_cast<float2*>(dst + wn + 2 * tq)     = make_float2(ca[2], ca[3]);
            *reinterpret_cast<float2*>(dst + wn + 8 + 2 * tq) = make_float2(cb[2], cb[3]);
        }
    }
}

// ---------------------------------------------------------------------------
// Launch
// ---------------------------------------------------------------------------
extern "C" void kernel_launch(void* const* d_in, const int* in_sizes, int n_in,
                              void* d_out, int out_size)
{
    const float* inputs    = (const float*)d_in[0];   // [B,T,512]
    const float* mems      = (const float*)d_in[1];   // [B,S,256]
    const int*   mem_masks = (const int*)  d_in[2];   // [B]
    const float* Wq        = (const float*)d_in[3];   // [256,512]
    const float* Wc        = (const float*)d_in[4];   // [256,256]
    const float* bc        = (const float*)d_in[5];   // [256]
    const float* v         = (const float*)d_in[6];   // [256]
    const float* Wout      = (const float*)d_in[7];   // [512,768]
    const float* bout      = (const float*)d_in[8];   // [512]

    float* out = (float*)d_out;
    float* attn_h    = out;                                   // [B,T,512]
    float* align_vec = out + (size_t)BB * TT_ALL * IN_DIM;    // [B,T,S]

    float *p_wq = nullptr, *p_uh = nullptr, *p_c = nullptr;
    cudaGetSymbolAddress((void**)&p_wq, g_wq);
    cudaGetSymbolAddress((void**)&p_uh, g_uh);
    cudaGetSymbolAddress((void**)&p_c,  g_c);

    cudaFuncSetAttribute(attn_core_kernel,
                         cudaFuncAttributeMaxDynamicSharedMemorySize,
                         ATTN_SMEM_BYTES);

    const int M = BB * TT_ALL;   // 2048

    // 1+2) merged wq / uh GEMMs  (grid 4 x 64 = 256 CTAs, 256 thr)
    gemm_k1k2_kernel<<<dim3(MEM_DIM / GBN, 64), 256>>>(
        inputs, Wq, mems, Wc, bc, p_wq, p_uh);

    // 3) fused tanh-score / softmax / tensor-core context (148 CTAs)
    attn_core_kernel<<<dim3(NTILES_T, BB), 512, ATTN_SMEM_BYTES>>>(
        p_wq, p_uh, mems, mem_masks, v, align_vec, p_c);

    // 4) attn_h = [c, inputs] @ Wout^T + bout  (grid 8 x 32 = 256 CTAs, 256 thr)
    gemm_out_kernel<<<dim3(IN_DIM / GBN, M / GBM), 256>>>(
        p_c, inputs, Wout, bout, attn_h);
}

// round 9
// speedup vs baseline: 1.0496x; 1.0496x over previous
#include <cuda_runtime.h>
#include <cuda_bf16.h>
#include <cstdint>

// Problem constants
#define BB      4
#define TT_ALL  512
#define SS      512
#define IN_DIM  512
#define MEM_DIM 256

// Scratch (device globals; no allocations allowed)
__device__ __align__(16) float g_wq[BB * TT_ALL * MEM_DIM];   // [B,T,256]
__device__ __align__(16) float g_uh[BB * SS * MEM_DIM];       // [B,S,256]
__device__ __align__(16) float g_c [BB * TT_ALL * MEM_DIM];   // [B,T,256]

// ---------------------------------------------------------------------------
// cp.async helpers
// ---------------------------------------------------------------------------
__device__ __forceinline__ void cp_async16(void* sdst, const void* gsrc) {
    uint32_t sa = (uint32_t)__cvta_generic_to_shared(sdst);
    asm volatile("cp.async.ca.shared.global [%0], [%1], 16;\n" :: "r"(sa), "l"(gsrc));
}
#define CP_COMMIT()  asm volatile("cp.async.commit_group;\n")
#define CP_WAIT(N)   asm volatile("cp.async.wait_group %0;\n" :: "n"(N))

__device__ __forceinline__ uint32_t f2tf32(float f) {
    uint32_t o;
    asm("cvt.rna.tf32.f32 %0, %1;" : "=r"(o) : "f"(f));
    return o;
}

__device__ __forceinline__ void mma_tf32(
    float& c0, float& c1, float& c2, float& c3,
    uint32_t a0, uint32_t a1, uint32_t a2, uint32_t a3,
    uint32_t b0, uint32_t b1)
{
    asm volatile(
        "mma.sync.aligned.m16n8k8.row.col.f32.tf32.tf32.f32 "
        "{%0,%1,%2,%3}, {%4,%5,%6,%7}, {%8,%9}, {%0,%1,%2,%3};\n"
        : "+f"(c0), "+f"(c1), "+f"(c2), "+f"(c3)
        : "r"(a0), "r"(a1), "r"(a2), "r"(a3), "r"(b0), "r"(b1));
}

// ---------------------------------------------------------------------------
// TF32 tensor-core NT GEMM, 4-stage cp.async pipeline:
// C[M,N] = Acat[M,K] * B[N,K]^T (+bias)
// CTA tile 64x64, BK=32, 128 threads = 4 warps, warp tile 32x32.
// Operands are raw fp32 in smem, read as tf32 (truncation) by mma.
// Dual-A: rows with k < K1 from A (pitch K1), k >= K1 from A2 (pitch K-K1).
// ---------------------------------------------------------------------------
#define GBM 64
#define GBN 64
#define GBK 32
#define SPITCH 36
#define NSTAGE 4

struct GemmSmem {
    float As[NSTAGE][GBM][SPITCH];
    float Bs[NSTAGE][GBN][SPITCH];
};
#define GEMM_SMEM_BYTES ((int)sizeof(GemmSmem))   // 73728

__device__ __forceinline__ void gemm_issue_stage(
    GemmSmem* sm, int stage,
    const float* __restrict__ A, const float* __restrict__ A2, int K1,
    const float* __restrict__ Bm, int K, int row0, int col0, int k0, int tid)
{
    const int srow = tid >> 3;          // 0..15
    const int sc4  = (tid & 7) * 4;     // 0..28 step 4

    const float* srcA = A; int pitchA = K1; int kcol = k0;
    if (A2 != nullptr && k0 >= K1) { srcA = A2; pitchA = K - K1; kcol = k0 - K1; }
#pragma unroll
    for (int i = 0; i < 4; i++)
        cp_async16(&sm->As[stage][srow + 16 * i][sc4],
                   srcA + (size_t)(row0 + srow + 16 * i) * pitchA + kcol + sc4);
#pragma unroll
    for (int i = 0; i < 4; i++)
        cp_async16(&sm->Bs[stage][srow + 16 * i][sc4],
                   Bm + (size_t)(col0 + srow + 16 * i) * K + k0 + sc4);
}

__device__ __forceinline__ void gemm_body(
    GemmSmem* sm,
    const float* __restrict__ A, const float* __restrict__ A2, int K1,
    const float* __restrict__ Bm, const float* __restrict__ bias,
    float* __restrict__ C, int N, int K, int row0, int col0)
{
    const int tid  = threadIdx.x;
    const int wid  = tid >> 5;
    const int lane = tid & 31;
    const int g    = lane >> 2;
    const int t    = lane & 3;
    const int wrow = (wid & 1) * 32;
    const int wcol = (wid >> 1) * 32;

    const int NP = K / GBK;

    float acc[2][4][4];
#pragma unroll
    for (int mt = 0; mt < 2; mt++)
#pragma unroll
        for (int nt = 0; nt < 4; nt++)
#pragma unroll
            for (int i = 0; i < 4; i++) acc[mt][nt][i] = 0.f;

    // prologue: issue stages 0..2 (NP >= 3 for all our shapes)
#pragma unroll
    for (int s = 0; s < NSTAGE - 1; s++) {
        gemm_issue_stage(sm, s, A, A2, K1, Bm, K, row0, col0, s * GBK, tid);
        CP_COMMIT();
    }

    for (int p = 0; p < NP; p++) {
        CP_WAIT(2);            // stage p landed
        __syncthreads();

        const float* ab = &sm->As[p & (NSTAGE - 1)][0][0];
        const float* bb = &sm->Bs[p & (NSTAGE - 1)][0][0];
#pragma unroll
        for (int kk = 0; kk < GBK; kk += 8) {
            uint32_t af[2][4], bf[4][2];
#pragma unroll
            for (int mt = 0; mt < 2; mt++) {
                const int r = wrow + 16 * mt + g;
                af[mt][0] = __float_as_uint(ab[(r)     * SPITCH + kk + t]);
                af[mt][1] = __float_as_uint(ab[(r + 8) * SPITCH + kk + t]);
                af[mt][2] = __float_as_uint(ab[(r)     * SPITCH + kk + t + 4]);
                af[mt][3] = __float_as_uint(ab[(r + 8) * SPITCH + kk + t + 4]);
            }
#pragma unroll
            for (int nt = 0; nt < 4; nt++) {
                const int n = wcol + 8 * nt + g;
                bf[nt][0] = __float_as_uint(bb[n * SPITCH + kk + t]);
                bf[nt][1] = __float_as_uint(bb[n * SPITCH + kk + t + 4]);
            }
#pragma unroll
            for (int mt = 0; mt < 2; mt++)
#pragma unroll
                for (int nt = 0; nt < 4; nt++)
                    mma_tf32(acc[mt][nt][0], acc[mt][nt][1],
                             acc[mt][nt][2], acc[mt][nt][3],
                             af[mt][0], af[mt][1], af[mt][2], af[mt][3],
                             bf[nt][0], bf[nt][1]);
        }
        __syncthreads();       // all warps done reading stage p before refill

        // issue stage p+3 (or empty group to keep wait_group accounting)
        if (p + NSTAGE - 1 < NP)
            gemm_issue_stage(sm, (p + NSTAGE - 1) & (NSTAGE - 1),
                             A, A2, K1, Bm, K, row0, col0,
                             (p + NSTAGE - 1) * GBK, tid);
        CP_COMMIT();
    }

    // epilogue
#pragma unroll
    for (int mt = 0; mt < 2; mt++) {
        const int row = row0 + wrow + 16 * mt + g;
#pragma unroll
        for (int nt = 0; nt < 4; nt++) {
            const int col = col0 + wcol + 8 * nt + 2 * t;
            float b0v = 0.f, b1v = 0.f;
            if (bias != nullptr) { b0v = bias[col]; b1v = bias[col + 1]; }
            C[(size_t)row * N + col]           = acc[mt][nt][0] + b0v;
            C[(size_t)row * N + col + 1]       = acc[mt][nt][1] + b1v;
            C[(size_t)(row + 8) * N + col]     = acc[mt][nt][2] + b0v;
            C[(size_t)(row + 8) * N + col + 1] = acc[mt][nt][3] + b1v;
        }
    }
}

// merged k1+k2: grid (4, 64). by<32 -> wq GEMM, else uh GEMM.
__global__ __launch_bounds__(128) void gemm_k1k2_kernel(
    const float* __restrict__ inputs, const float* __restrict__ Wq,
    const float* __restrict__ mems,   const float* __restrict__ Wc,
    const float* __restrict__ bc,
    float* __restrict__ owq, float* __restrict__ ouh)
{
    extern __shared__ GemmSmem sm_dyn[];
    const int bx = blockIdx.x, by = blockIdx.y;
    if (by < 32) {
        gemm_body(sm_dyn, inputs, nullptr, IN_DIM, Wq, nullptr, owq,
                  MEM_DIM, IN_DIM, by * GBM, bx * GBN);
    } else {
        gemm_body(sm_dyn, mems, nullptr, MEM_DIM, Wc, bc, ouh,
                  MEM_DIM, MEM_DIM, (by - 32) * GBM, bx * GBN);
    }
}

// k4: dual-A output projection. grid (8, 32)
__global__ __launch_bounds__(128) void gemm_out_kernel(
    const float* __restrict__ Cmat, const float* __restrict__ inputs,
    const float* __restrict__ Wout, const float* __restrict__ bout,
    float* __restrict__ attn_h)
{
    extern __shared__ GemmSmem sm_dyn[];
    gemm_body(sm_dyn, Cmat, inputs, MEM_DIM, Wout, bout, attn_h,
              IN_DIM, MEM_DIM + IN_DIM, blockIdx.y * GBM, blockIdx.x * GBN);
}

// ---------------------------------------------------------------------------
// Fused attention core (unchanged from R7): scores -> tanh -> dot(v) ->
// masked softmax -> tensor-core context. Grid (37, B) = 148 CTAs, 512 thr.
// ---------------------------------------------------------------------------
#define TTILE 14
#define NTILES_T 37
#define DTILE 16
#define UPITCH 20
#define UBUF_ELEMS (SS * UPITCH)
#define PBP   520
#define MROWS 32
#define MPITCH 264
#define MBUF_ELEMS (MROWS * MPITCH)
#define ATTN_SMEM_FLOATS (2 * UBUF_ELEMS + TTILE * MEM_DIM + MEM_DIM + TTILE * 16 \
                          + 2 * MBUF_ELEMS)
#define ATTN_SMEM_BYTES  (ATTN_SMEM_FLOATS * 4)

__device__ __forceinline__ float tanh_fast(float x) {
    float y;
    asm("tanh.approx.f32 %0, %1;" : "=f"(y) : "f"(x));
    return y;
}

__device__ __forceinline__ void prefetch_uh(
    const float* __restrict__ uh_b, float* ubuf, int d0, int tid)
{
    const int c  = tid & 3;
    const int s0 = tid >> 2;
#pragma unroll
    for (int it = 0; it < 4; it++) {
        const int s = s0 + it * 128;
        cp_async16(ubuf + s * UPITCH + c * 4,
                   uh_b + ((size_t)s << 8) + d0 + c * 4);
    }
}

__device__ __forceinline__ void stage_mems(
    const float* __restrict__ memb, float* mbuf, int chunk, int tid)
{
#pragma unroll
    for (int j = 0; j < 4; j++) {
        const int i  = tid + j * 512;
        const int r  = i >> 6;
        const int c4 = (i & 63) * 4;
        cp_async16(mbuf + r * MPITCH + c4,
                   memb + ((size_t)(chunk * MROWS + r) << 8) + c4);
    }
}

__global__ __launch_bounds__(512) void attn_core_kernel(
    const float* __restrict__ wq,        // [B,T,256]
    const float* __restrict__ uh,        // [B,S,256]
    const float* __restrict__ mems,      // [B,S,256]
    const int*   __restrict__ mem_masks, // [B]
    const float* __restrict__ v,         // [256]
    float* __restrict__ align_out,       // [B,T,S]
    float* __restrict__ c_out)           // [B,T,256]
{
    extern __shared__ float sdyn[];
    float* ubuf0 = sdyn;
    float* ubuf1 = sdyn + UBUF_ELEMS;
    float* wq_s  = sdyn + 2 * UBUF_ELEMS;
    float* v_s   = wq_s + TTILE * MEM_DIM;
    float* red_s = v_s + MEM_DIM;
    float* mbuf0 = red_s + TTILE * 16;
    float* mbuf1 = mbuf0 + MBUF_ELEMS;
    float* pbuf  = ubuf0;

    const int tid  = threadIdx.x;
    const int b    = blockIdx.y;
    const int t0   = blockIdx.x * TTILE;
    const int my_s = tid;
    const int lane = tid & 31;
    const int wid  = tid >> 5;

    const float* uh_b = uh + ((size_t)b * SS << 8);

    prefetch_uh(uh_b, ubuf0, 0, tid);
    CP_COMMIT();

    for (int i = tid; i < TTILE * 64; i += 512) {
        const int t  = i >> 6;
        const int c4 = (i & 63) * 4;
        float4 val = make_float4(0.f, 0.f, 0.f, 0.f);
        if (t0 + t < TT_ALL)
            val = *reinterpret_cast<const float4*>(
                wq + ((size_t)(b * TT_ALL + t0 + t) << 8) + c4);
        *reinterpret_cast<float4*>(wq_s + t * MEM_DIM + c4) = val;
    }
    if (tid < 64)
        *reinterpret_cast<float4*>(v_s + tid * 4) =
            *reinterpret_cast<const float4*>(v + tid * 4);

    const int mlen = mem_masks[b];

    float acc[TTILE];
#pragma unroll
    for (int t = 0; t < TTILE; t++) acc[t] = 0.f;

#pragma unroll 1
    for (int tile = 0; tile < MEM_DIM / DTILE; tile++) {
        const int d0 = tile * DTILE;
        if (tile + 1 < MEM_DIM / DTILE) {
            prefetch_uh(uh_b, (tile & 1) ? ubuf0 : ubuf1, d0 + DTILE, tid);
            CP_COMMIT();
            CP_WAIT(1);
        } else {
            CP_WAIT(0);
        }
        __syncthreads();

        const float* ub = ((tile & 1) ? ubuf1 : ubuf0) + my_s * UPITCH;
#pragma unroll
        for (int q = 0; q < 4; q++) {
            const float4 u4 = *reinterpret_cast<const float4*>(ub + q * 4);
            const float4 v4 = *reinterpret_cast<const float4*>(v_s + d0 + q * 4);
#pragma unroll
            for (int t = 0; t < TTILE; t++) {
                const float4 w4 = *reinterpret_cast<const float4*>(
                    wq_s + t * MEM_DIM + d0 + q * 4);
                float a = acc[t];
                a = fmaf(tanh_fast(w4.x + u4.x), v4.x, a);
                a = fmaf(tanh_fast(w4.y + u4.y), v4.y, a);
                a = fmaf(tanh_fast(w4.z + u4.z), v4.z, a);
                a = fmaf(tanh_fast(w4.w + u4.w), v4.w, a);
                acc[t] = a;
            }
        }
        __syncthreads();
    }

    const bool valid = (my_s < mlen);
    float sc[TTILE];
#pragma unroll
    for (int t = 0; t < TTILE; t++) sc[t] = valid ? acc[t] : -1e30f;

    float mx[TTILE];
#pragma unroll
    for (int t = 0; t < TTILE; t++) {
        float m = sc[t];
#pragma unroll
        for (int o = 16; o > 0; o >>= 1) m = fmaxf(m, __shfl_xor_sync(0xffffffffu, m, o));
        if (lane == 0) red_s[t * 16 + wid] = m;
    }
    __syncthreads();
#pragma unroll
    for (int t = 0; t < TTILE; t++) {
        float m = red_s[t * 16];
#pragma unroll
        for (int i = 1; i < 16; i++) m = fmaxf(m, red_s[t * 16 + i]);
        mx[t] = m;
    }
    __syncthreads();

    float e[TTILE];
#pragma unroll
    for (int t = 0; t < TTILE; t++)
        e[t] = valid ? __expf(sc[t] - mx[t]) : 0.f;

#pragma unroll
    for (int t = 0; t < TTILE; t++) {
        float s = e[t];
#pragma unroll
        for (int o = 16; o > 0; o >>= 1) s += __shfl_xor_sync(0xffffffffu, s, o);
        if (lane == 0) red_s[t * 16 + wid] = s;
    }
    __syncthreads();

    float p[TTILE];
#pragma unroll
    for (int t = 0; t < TTILE; t++) {
        float s = 0.f;
#pragma unroll
        for (int i = 0; i < 16; i++) s += red_s[t * 16 + i];
        p[t] = e[t] * (1.0f / s);
    }

#pragma unroll
    for (int t = 0; t < TTILE; t++) {
        if (t0 + t < TT_ALL)
            align_out[((size_t)(b * TT_ALL + t0 + t) << 9) + my_s] = p[t];
        pbuf[t * PBP + my_s] = __uint_as_float(f2tf32(p[t]));
    }
    for (int i = tid; i < 2 * PBP; i += 512)
        pbuf[TTILE * PBP + i] = 0.f;
    __syncthreads();

    // ---- context via tensor cores ----
    const float* memb = mems + ((size_t)b * SS << 8);
    const int g  = lane >> 2;
    const int tq = lane & 3;
    const int wn = wid * 16;

    float ca[4] = {0.f, 0.f, 0.f, 0.f};
    float cb[4] = {0.f, 0.f, 0.f, 0.f};

    stage_mems(memb, mbuf0, 0, tid);
    CP_COMMIT();

#pragma unroll 1
    for (int ch = 0; ch < SS / MROWS; ch++) {
        if (ch + 1 < SS / MROWS) {
            stage_mems(memb, (ch & 1) ? mbuf0 : mbuf1, ch + 1, tid);
            CP_COMMIT();
            CP_WAIT(1);
        } else {
            CP_WAIT(0);
        }
        __syncthreads();

        const float* mb = (ch & 1) ? mbuf1 : mbuf0;
        const int sbase = ch * MROWS;
#pragma unroll
        for (int kk = 0; kk < MROWS; kk += 8) {
            const int sg = sbase + kk;
            uint32_t a0 = __float_as_uint(pbuf[(g)     * PBP + sg + tq]);
            uint32_t a1 = __float_as_uint(pbuf[(g + 8) * PBP + sg + tq]);
            uint32_t a2 = __float_as_uint(pbuf[(g)     * PBP + sg + tq + 4]);
            uint32_t a3 = __float_as_uint(pbuf[(g + 8) * PBP + sg + tq + 4]);

            uint32_t b0 = __float_as_uint(mb[(kk + tq)     * MPITCH + wn + g]);
            uint32_t b1 = __float_as_uint(mb[(kk + tq + 4) * MPITCH + wn + g]);
            mma_tf32(ca[0], ca[1], ca[2], ca[3], a0, a1, a2, a3, b0, b1);

            b0 = __float_as_uint(mb[(kk + tq)     * MPITCH + wn + 8 + g]);
            b1 = __float_as_uint(mb[(kk + tq + 4) * MPITCH + wn + 8 + g]);
            mma_tf32(cb[0], cb[1], cb[2], cb[3], a0, a1, a2, a3, b0, b1);
        }
        __syncthreads();
    }

    {
        const int row0g = t0 + g;
        if (row0g < TT_ALL) {
            float* dst = c_out + ((size_t)(b * TT_ALL + row0g) << 8);
            *reinterpret_cast<float2*>(dst + wn + 2 * tq)     = make_float2(ca[0], ca[1]);
            *reinterpret_cast<float2*>(dst + wn + 8 + 2 * tq) = make_float2(cb[0], cb[1]);
        }
        const int row1g = t0 + g + 8;
        if (g + 8 < TTILE && row1g < TT_ALL) {
            float* dst = c_out + ((size_t)(b * TT_ALL + row1g) << 8);
            *reinterpret_cast<float2*>(dst + wn + 2 * tq)     = make_float2(ca[2], ca[3]);
            *reinterpret_cast<float2*>(dst + wn + 8 + 2 * tq) = make_float2(cb[2], cb[3]);
        }
    }
}

// ---------------------------------------------------------------------------
// Launch
// ---------------------------------------------------------------------------
extern "C" void kernel_launch(void* const* d_in, const int* in_sizes, int n_in,
                              void* d_out, int out_size)
{
    const float* inputs    = (const float*)d_in[0];   // [B,T,512]
    const float* mems      = (const float*)d_in[1];   // [B,S,256]
    const int*   mem_masks = (const int*)  d_in[2];   // [B]
    const float* Wq        = (const float*)d_in[3];   // [256,512]
    const float* Wc        = (const float*)d_in[4];   // [256,256]
    const float* bc        = (const float*)d_in[5];   // [256]
    const float* v         = (const float*)d_in[6];   // [256]
    const float* Wout      = (const float*)d_in[7];   // [512,768]
    const float* bout      = (const float*)d_in[8];   // [512]

    float* out = (float*)d_out;
    float* attn_h    = out;                                   // [B,T,512]
    float* align_vec = out + (size_t)BB * TT_ALL * IN_DIM;    // [B,T,S]

    float *p_wq = nullptr, *p_uh = nullptr, *p_c = nullptr;
    cudaGetSymbolAddress((void**)&p_wq, g_wq);
    cudaGetSymbolAddress((void**)&p_uh, g_uh);
    cudaGetSymbolAddress((void**)&p_c,  g_c);

    cudaFuncSetAttribute(attn_core_kernel,
                         cudaFuncAttributeMaxDynamicSharedMemorySize,
                         ATTN_SMEM_BYTES);
    cudaFuncSetAttribute(gemm_k1k2_kernel,
                         cudaFuncAttributeMaxDynamicSharedMemorySize,
                         GEMM_SMEM_BYTES);
    cudaFuncSetAttribute(gemm_out_kernel,
                         cudaFuncAttributeMaxDynamicSharedMemorySize,
                         GEMM_SMEM_BYTES);

    const int M = BB * TT_ALL;   // 2048

    // 1+2) merged wq / uh GEMMs  (grid 4 x 64 = 256 CTAs, 128 thr)
    gemm_k1k2_kernel<<<dim3(MEM_DIM / GBN, 64), 128, GEMM_SMEM_BYTES>>>(
        inputs, Wq, mems, Wc, bc, p_wq, p_uh);

    // 3) fused tanh-score / softmax / tensor-core context (148 CTAs)
    attn_core_kernel<<<dim3(NTILES_T, BB), 512, ATTN_SMEM_BYTES>>>(
        p_wq, p_uh, mems, mem_masks, v, align_vec, p_c);

    // 4) attn_h = [c, inputs] @ Wout^T + bout  (grid 8 x 32 = 256 CTAs, 128 thr)
    gemm_out_kernel<<<dim3(IN_DIM / GBN, M / GBM), 128, GEMM_SMEM_BYTES>>>(
        p_c, inputs, Wout, bout, attn_h);
}